// round 12
// baseline (speedup 1.0000x reference)
#include <cuda_runtime.h>
#include <cuda_bf16.h>
#include <cstdint>

// Problem constants:
//   N=50000 nodes, E=800000 edges, IN_DIM=128, H=8, D=16 -> C = H*D = 128
// (resubmission of the previous round's source; prior bench died to a broker
//  infra failure before any harness output)
#define NN 50000
#define EE 800000
#define CC 128
#define KK 128

typedef unsigned long long ull;

// ---------------- device scratch (zero-initialized at module load) ----------
__device__ float d_z[NN * CC];          // per-node projected features [N,128]
__device__ int   d_cnt[NN];             // degree hist -> scatter cursor (tail-zeroed)
__device__ int   d_off[NN + 1];         // CSR row offsets by dst
__device__ int   d_csr_src[EE];         // src ids grouped by dst

#define SB   512
#define NBLK ((NN + SB - 1) / SB)       // 98
__device__ int d_btot[NBLK];            // per-block totals from scan1

// ---------------- packed f32x2 helpers --------------------------------------
__device__ __forceinline__ ull fma2(ull a, ull b, ull c) {
    ull d;
    asm("fma.rn.f32x2 %0, %1, %2, %3;" : "=l"(d) : "l"(a), "l"(b), "l"(c));
    return d;
}
__device__ __forceinline__ ull mul2(ull a, ull b) {
    ull d;
    asm("mul.rn.f32x2 %0, %1, %2;" : "=l"(d) : "l"(a), "l"(b));
    return d;
}
__device__ __forceinline__ ull add2(ull a, ull b) {
    ull d;
    asm("add.rn.f32x2 %0, %1, %2;" : "=l"(d) : "l"(a), "l"(b));
    return d;
}
__device__ __forceinline__ ull pack2(float x) {
    ull d;
    asm("mov.b64 %0, {%1, %1};" : "=l"(d) : "f"(x));
    return d;
}
__device__ __forceinline__ ull packf(float lo, float hi) {
    ull d;
    asm("mov.b64 %0, {%1, %2};" : "=l"(d) : "f"(lo), "f"(hi));
    return d;
}
__device__ __forceinline__ void unpackf(ull v, float& lo, float& hi) {
    asm("mov.b64 {%0, %1}, %2;" : "=f"(lo), "=f"(hi) : "l"(v));
}

// ---------------- CSR construction ------------------------------------------
// Requires d_cnt == 0 on entry (module load on call 1; tail-zero thereafter).
__global__ void k_hist(const int4* __restrict__ dst4) {
    int t = blockIdx.x * blockDim.x + threadIdx.x;
    if (t < EE / 4) {
        int4 d = __ldg(&dst4[t]);
        atomicAdd(&d_cnt[d.x], 1);
        atomicAdd(&d_cnt[d.y], 1);
        atomicAdd(&d_cnt[d.z], 1);
        atomicAdd(&d_cnt[d.w], 1);
    }
}

__global__ void __launch_bounds__(SB) k_scan1() {
    __shared__ int s[SB];
    const int b = blockIdx.x, t = threadIdx.x, i = b * SB + t;
    int v = (i < NN) ? d_cnt[i] : 0;
    s[t] = v;
    __syncthreads();
    for (int o = 1; o < SB; o <<= 1) {
        int x = (t >= o) ? s[t - o] : 0;
        __syncthreads();
        s[t] += x;
        __syncthreads();
    }
    if (i < NN) d_off[i] = s[t] - v;
    if (t == SB - 1) d_btot[b] = s[t];
}

// Every block redundantly scans the 98 block totals (no inter-block spin).
__global__ void __launch_bounds__(SB) k_scan3() {
    __shared__ int sb[128];
    const int b = blockIdx.x, t = threadIdx.x, i = b * SB + t;

    if (t < 128) sb[t] = (t < NBLK) ? d_btot[t] : 0;
    __syncthreads();
    for (int o = 1; o < 128; o <<= 1) {
        int x = (t < 128 && t >= o) ? sb[t - o] : 0;
        __syncthreads();
        if (t < 128) sb[t] += x;
        __syncthreads();
    }
    const int boff = (b > 0) ? sb[b - 1] : 0;

    if (i < NN) {
        int o = d_off[i] + boff;
        d_off[i] = o;
        d_cnt[i] = o;
    }
    if (b == NBLK - 1 && t == 0) d_off[NN] = EE;
}

__global__ void k_scatter(const int* __restrict__ src, const int* __restrict__ dst) {
    int e = blockIdx.x * blockDim.x + threadIdx.x;
    if (e < EE) {
        int pos = atomicAdd(&d_cnt[dst[e]], 1);
        d_csr_src[pos] = src[e];
    }
}

__global__ void k_tail_zero() {
    int i = blockIdx.x * blockDim.x + threadIdx.x;
    if (i < NN) d_cnt[i] = 0;
}

// ---------------- GEMM via packed fma.rn.f32x2 ------------------------------
#define GBM 64

__global__ void __launch_bounds__(256) k_gemm(const float* __restrict__ hin,
                                              const float* __restrict__ Wfc) {
    extern __shared__ float smem[];
    float* sW = smem;                  // [128][128]  sW[k*128 + c]
    float* sH = smem + KK * CC;        // [64][128]   sH[node*128 + k]

    const int tid  = threadIdx.x;
    const int lane = tid & 31;
    const int warp = tid >> 5;
    const int base = blockIdx.x * GBM;
    const int n0   = warp * 8;

    {
        const float4* W4 = (const float4*)Wfc;
        float4* sW4 = (float4*)sW;
        for (int g = tid; g < KK * CC / 4; g += 256) {
            int k  = g >> 5;
            int hh = (g >> 2) & 7;
            int dq = g & 3;
            sW4[g] = W4[hh * 512 + k * 4 + dq];
        }
    }
    {
        const float4* H4 = (const float4*)hin;
        float4* sH4 = (float4*)sH;
        for (int g = tid; g < GBM * KK / 4; g += 256) {
            int row = g >> 5;
            int kq  = g & 31;
            int gn  = base + row;
            sH4[g] = (gn < NN) ? H4[gn * 32 + kq]
                               : make_float4(0.f, 0.f, 0.f, 0.f);
        }
    }
    __syncthreads();

    ull acc[8][2];
#pragma unroll
    for (int j = 0; j < 8; ++j) { acc[j][0] = 0ull; acc[j][1] = 0ull; }

    for (int k = 0; k < KK; k += 4) {
        ull w2[4][2];
#pragma unroll
        for (int kk = 0; kk < 4; ++kk) {
            ulonglong2 wv = *(const ulonglong2*)&sW[(k + kk) * CC + lane * 4];
            w2[kk][0] = wv.x;
            w2[kk][1] = wv.y;
        }
#pragma unroll
        for (int j = 0; j < 8; ++j) {
            const float4 hj = *(const float4*)&sH[(n0 + j) * KK + k];
            ull h0 = pack2(hj.x), h1 = pack2(hj.y), h2 = pack2(hj.z), h3 = pack2(hj.w);
            acc[j][0] = fma2(h0, w2[0][0], acc[j][0]);
            acc[j][1] = fma2(h0, w2[0][1], acc[j][1]);
            acc[j][0] = fma2(h1, w2[1][0], acc[j][0]);
            acc[j][1] = fma2(h1, w2[1][1], acc[j][1]);
            acc[j][0] = fma2(h2, w2[2][0], acc[j][0]);
            acc[j][1] = fma2(h2, w2[2][1], acc[j][1]);
            acc[j][0] = fma2(h3, w2[3][0], acc[j][0]);
            acc[j][1] = fma2(h3, w2[3][1], acc[j][1]);
        }
    }

#pragma unroll
    for (int j = 0; j < 8; ++j) {
        int gn = base + n0 + j;
        if (gn < NN) {
            float2 lo = *(float2*)&acc[j][0];
            float2 hi = *(float2*)&acc[j][1];
            *(float4*)&d_z[gn * CC + lane * 4] = make_float4(lo.x, lo.y, hi.x, hi.y);
        }
    }
}

// ---------------- per-dst-node softmax aggregation + epilogue ---------------
// TWO warps per node; each warp owns 64 channels, lane owns 2 channels packed
// into one f32x2 accumulator pair. Per edge per lane: 1 mul2 + 2 MUFU +
// 1 add2 + 1 fma2 (vs 12 scalar FMA + 4 MUFU for 4 channels before).
// Per-channel arithmetic and association identical to the previous version.
__device__ __forceinline__ float elu1(float v) {
    return v > 0.f ? v : expm1f(v);
}

__device__ __forceinline__ void edge_accum2(ull za, ull zds2, ull& d2, ull& n2) {
    ull e2 = mul2(za, zds2);
    float lo, hi;
    unpackf(e2, lo, hi);
    lo = exp2f(lo);
    hi = exp2f(hi);
    ull ex2 = packf(lo, hi);
    d2 = add2(d2, ex2);
    n2 = fma2(ex2, za, n2);
}

__global__ void __launch_bounds__(256) k_agg(const float* __restrict__ hin,
                                             const float* __restrict__ snorm,
                                             float* __restrict__ out) {
    const int gwarp = (blockIdx.x * blockDim.x + threadIdx.x) >> 5;
    const int lane  = threadIdx.x & 31;
    if (gwarp >= NN * 2) return;
    const int node  = gwarp >> 1;
    const int cbase = (gwarp & 1) * 64 + lane * 2;   // this lane's 2 channels

    const float LOG2E = 1.4426950408889634f;
    const ull zdraw = *(const ull*)&d_z[node * CC + cbase];
    const ull zds2  = mul2(zdraw, pack2(LOG2E));

    ull d2 = 0ull, n2 = 0ull;

    const int p0 = d_off[node];
    const int p1 = d_off[node + 1];

    int p = p0;
    for (; p + 3 < p1; p += 4) {
        int s0 = __ldg(&d_csr_src[p]);
        int s1 = __ldg(&d_csr_src[p + 1]);
        int s2 = __ldg(&d_csr_src[p + 2]);
        int s3 = __ldg(&d_csr_src[p + 3]);
        ull z0 = *(const ull*)&d_z[s0 * CC + cbase];
        ull z1 = *(const ull*)&d_z[s1 * CC + cbase];
        ull z2 = *(const ull*)&d_z[s2 * CC + cbase];
        ull z3 = *(const ull*)&d_z[s3 * CC + cbase];
        edge_accum2(z0, zds2, d2, n2);
        edge_accum2(z1, zds2, d2, n2);
        edge_accum2(z2, zds2, d2, n2);
        edge_accum2(z3, zds2, d2, n2);
    }
    for (; p < p1; ++p) {
        int s0 = __ldg(&d_csr_src[p]);
        ull z0 = *(const ull*)&d_z[s0 * CC + cbase];
        edge_accum2(z0, zds2, d2, n2);
    }

    const float sn = __ldg(&snorm[node]);
    const float2 hv = *(const float2*)&hin[node * CC + cbase];

    float dx, dy, nx, ny;
    unpackf(d2, dx, dy);
    unpackf(n2, nx, ny);

    float rx = (dx > 0.f) ? __fdividef(1.f, dx) : 0.f;
    float ry = (dy > 0.f) ? __fdividef(1.f, dy) : 0.f;

    float2 o;
    o.x = hv.x + elu1(nx * rx * sn);
    o.y = hv.y + elu1(ny * ry * sn);

    *(float2*)&out[node * CC + cbase] = o;
}

// ---------------- launch ----------------------------------------------------
// Fork/join for capture: s2's chain is gemm -> evJoin -> (wait evScat) ->
// tail_zero -> evTail. Stream 0 waits evJoin before agg and evTail after agg,
// so the side branch is fully joined when kernel_launch returns.
extern "C" void kernel_launch(void* const* d_in, const int* in_sizes, int n_in,
                              void* d_out, int out_size) {
    const float* hin   = (const float*)d_in[0];   // [N,128]
    const float* snorm = (const float*)d_in[1];   // [N,1]
    const float* Wfc   = (const float*)d_in[2];   // [8,128,16]
    const int*   src   = (const int*)d_in[3];     // [E]
    const int*   dst   = (const int*)d_in[4];     // [E]
    float* out = (float*)d_out;                   // [N,128]

    const int gemm_smem = (KK * CC + GBM * KK) * sizeof(float);   // 96 KB

    static int init_done = 0;
    static cudaStream_t s2 = 0;
    static cudaEvent_t evFork = 0, evJoin = 0, evScat = 0, evTail = 0;
    if (!init_done) {
        cudaFuncSetAttribute(k_gemm, cudaFuncAttributeMaxDynamicSharedMemorySize,
                             gemm_smem);
        if (cudaStreamCreateWithFlags(&s2, cudaStreamNonBlocking) != cudaSuccess)
            s2 = 0;
        if (s2) {
            if (cudaEventCreateWithFlags(&evFork, cudaEventDisableTiming) != cudaSuccess ||
                cudaEventCreateWithFlags(&evJoin, cudaEventDisableTiming) != cudaSuccess ||
                cudaEventCreateWithFlags(&evScat, cudaEventDisableTiming) != cudaSuccess ||
                cudaEventCreateWithFlags(&evTail, cudaEventDisableTiming) != cudaSuccess) {
                s2 = 0;   // deterministic serial fallback
            }
        }
        init_done = 1;
    }

    if (s2) {
        cudaEventRecord(evFork, 0);
        cudaStreamWaitEvent(s2, evFork, 0);
        k_gemm<<<(NN + GBM - 1) / GBM, 256, gemm_smem, s2>>>(hin, Wfc);
        cudaEventRecord(evJoin, s2);
    }

    // CSR chain on the default stream (d_cnt == 0 invariant on entry).
    k_hist<<<(EE / 4 + 255) / 256, 256>>>((const int4*)dst);
    k_scan1<<<NBLK, SB>>>();
    k_scan3<<<NBLK, SB>>>();
    k_scatter<<<(EE + 255) / 256, 256>>>(src, dst);

    if (s2) {
        cudaEventRecord(evScat, 0);
        cudaStreamWaitEvent(s2, evScat, 0);              // after last d_cnt use
        k_tail_zero<<<(NN + 255) / 256, 256, 0, s2>>>(); // overlaps agg
        cudaEventRecord(evTail, s2);
        cudaStreamWaitEvent(0, evJoin, 0);               // agg needs d_z
        k_agg<<<(NN * 2 * 32 + 255) / 256, 256>>>(hin, snorm, out);
        cudaStreamWaitEvent(0, evTail, 0);               // fully join s2
    } else {
        k_gemm<<<(NN + GBM - 1) / GBM, 256, gemm_smem>>>(hin, Wfc);
        k_agg<<<(NN * 2 * 32 + 255) / 256, 256>>>(hin, snorm, out);
        k_tail_zero<<<(NN + 255) / 256, 256>>>();
    }
}

// round 15
// speedup vs baseline: 1.0200x; 1.0200x over previous
#include <cuda_runtime.h>
#include <cuda_bf16.h>
#include <cstdint>

// GAT layer, fixed shapes: N=50000 nodes, E=800000 edges, C=H*D=128, K=128.
// Pipeline: CSR-by-dst build || f32x2 GEMM (forked stream), then warp-per-node
// segment softmax aggregation + graphnorm/ELU/residual epilogue.
#define NV 50000
#define NE 800000
#define NC 128
#define NK 128

typedef unsigned long long u64;

// ---------------- device scratch (zero-initialized at module load) ----------
__device__ float g_z[NV * NC];           // projected features [N,128]
__device__ int   g_cnt[NV];              // degree hist -> cursor (tail-zeroed)
__device__ int   g_off[NV + 1];          // CSR row offsets by dst
__device__ int   g_adj[NE];              // src ids grouped by dst

#define SCB  512
#define NSB  ((NV + SCB - 1) / SCB)      // 98
__device__ int g_btot[NSB];

// ---------------- packed f32x2 helpers --------------------------------------
__device__ __forceinline__ u64 vfma2(u64 a, u64 b, u64 c) {
    u64 r;
    asm("fma.rn.f32x2 %0, %1, %2, %3;" : "=l"(r) : "l"(a), "l"(b), "l"(c));
    return r;
}
__device__ __forceinline__ u64 vmul2(u64 a, u64 b) {
    u64 r;
    asm("mul.rn.f32x2 %0, %1, %2;" : "=l"(r) : "l"(a), "l"(b));
    return r;
}
__device__ __forceinline__ u64 vadd2(u64 a, u64 b) {
    u64 r;
    asm("add.rn.f32x2 %0, %1, %2;" : "=l"(r) : "l"(a), "l"(b));
    return r;
}
__device__ __forceinline__ u64 vsplat(float x) {
    u64 r;
    asm("mov.b64 %0, {%1, %1};" : "=l"(r) : "f"(x));
    return r;
}
__device__ __forceinline__ u64 vpack(float lo, float hi) {
    u64 r;
    asm("mov.b64 %0, {%1, %2};" : "=l"(r) : "f"(lo), "f"(hi));
    return r;
}
__device__ __forceinline__ void vunpack(u64 v, float& lo, float& hi) {
    asm("mov.b64 {%0, %1}, %2;" : "=f"(lo), "=f"(hi) : "l"(v));
}

// ---------------- CSR construction ------------------------------------------
// g_cnt must be all-zero on entry (module load first call; tail-zero after).
__global__ void gat_hist(const int4* __restrict__ dst4) {
    int t = blockIdx.x * blockDim.x + threadIdx.x;
    if (t < NE / 4) {
        int4 d = __ldg(&dst4[t]);
        atomicAdd(&g_cnt[d.x], 1);
        atomicAdd(&g_cnt[d.y], 1);
        atomicAdd(&g_cnt[d.z], 1);
        atomicAdd(&g_cnt[d.w], 1);
    }
}

__global__ void __launch_bounds__(SCB) gat_scan_local() {
    __shared__ int s[SCB];
    const int b = blockIdx.x, t = threadIdx.x, i = b * SCB + t;
    int v = (i < NV) ? g_cnt[i] : 0;
    s[t] = v;
    __syncthreads();
    for (int o = 1; o < SCB; o <<= 1) {
        int x = (t >= o) ? s[t - o] : 0;
        __syncthreads();
        s[t] += x;
        __syncthreads();
    }
    if (i < NV) g_off[i] = s[t] - v;
    if (t == SCB - 1) g_btot[b] = s[t];
}

// Each block redundantly scans all 98 block totals (no inter-block spin).
__global__ void __launch_bounds__(SCB) gat_scan_apply() {
    __shared__ int sb[128];
    const int b = blockIdx.x, t = threadIdx.x, i = b * SCB + t;

    if (t < 128) sb[t] = (t < NSB) ? g_btot[t] : 0;
    __syncthreads();
    for (int o = 1; o < 128; o <<= 1) {
        int x = (t < 128 && t >= o) ? sb[t - o] : 0;
        __syncthreads();
        if (t < 128) sb[t] += x;
        __syncthreads();
    }
    const int boff = (b > 0) ? sb[b - 1] : 0;

    if (i < NV) {
        int o = g_off[i] + boff;
        g_off[i] = o;
        g_cnt[i] = o;                     // becomes scatter cursor
    }
    if (b == NSB - 1 && t == 0) g_off[NV] = NE;
}

__global__ void gat_scatter(const int* __restrict__ src, const int* __restrict__ dst) {
    int e = blockIdx.x * blockDim.x + threadIdx.x;
    if (e < NE) {
        int pos = atomicAdd(&g_cnt[dst[e]], 1);
        g_adj[pos] = src[e];
    }
}

__global__ void gat_reset() {
    int i = blockIdx.x * blockDim.x + threadIdx.x;
    if (i < NV) g_cnt[i] = 0;
}

// ---------------- GEMM via packed fma.rn.f32x2 ------------------------------
#define TM 64

__global__ void __launch_bounds__(256) gat_gemm(const float* __restrict__ hin,
                                                const float* __restrict__ Wfc) {
    extern __shared__ float smem[];
    float* sW = smem;                   // [128][128]  sW[k*128 + c]
    float* sH = smem + NK * NC;         // [64][128]   sH[row*128 + k]

    const int tid  = threadIdx.x;
    const int lane = tid & 31;
    const int warp = tid >> 5;
    const int base = blockIdx.x * TM;
    const int r0   = warp * 8;

    {
        const float4* W4 = (const float4*)Wfc;
        float4* sW4 = (float4*)sW;
        for (int g = tid; g < NK * NC / 4; g += 256) {
            int k  = g >> 5;
            int hh = (g >> 2) & 7;
            int dq = g & 3;
            sW4[g] = W4[hh * 512 + k * 4 + dq];
        }
    }
    {
        const float4* H4 = (const float4*)hin;
        float4* sH4 = (float4*)sH;
        for (int g = tid; g < TM * NK / 4; g += 256) {
            int row = g >> 5;
            int kq  = g & 31;
            int gn  = base + row;
            sH4[g] = (gn < NV) ? H4[gn * 32 + kq]
                               : make_float4(0.f, 0.f, 0.f, 0.f);
        }
    }
    __syncthreads();

    u64 acc[8][2];
#pragma unroll
    for (int j = 0; j < 8; ++j) { acc[j][0] = 0ull; acc[j][1] = 0ull; }

    for (int k = 0; k < NK; k += 4) {
        u64 w2[4][2];
#pragma unroll
        for (int kk = 0; kk < 4; ++kk) {
            ulonglong2 wv = *(const ulonglong2*)&sW[(k + kk) * NC + lane * 4];
            w2[kk][0] = wv.x;
            w2[kk][1] = wv.y;
        }
#pragma unroll
        for (int j = 0; j < 8; ++j) {
            const float4 hj = *(const float4*)&sH[(r0 + j) * NK + k];
            u64 h0 = vsplat(hj.x), h1 = vsplat(hj.y);
            u64 h2 = vsplat(hj.z), h3 = vsplat(hj.w);
            acc[j][0] = vfma2(h0, w2[0][0], acc[j][0]);
            acc[j][1] = vfma2(h0, w2[0][1], acc[j][1]);
            acc[j][0] = vfma2(h1, w2[1][0], acc[j][0]);
            acc[j][1] = vfma2(h1, w2[1][1], acc[j][1]);
            acc[j][0] = vfma2(h2, w2[2][0], acc[j][0]);
            acc[j][1] = vfma2(h2, w2[2][1], acc[j][1]);
            acc[j][0] = vfma2(h3, w2[3][0], acc[j][0]);
            acc[j][1] = vfma2(h3, w2[3][1], acc[j][1]);
        }
    }

#pragma unroll
    for (int j = 0; j < 8; ++j) {
        int gn = base + r0 + j;
        if (gn < NV) {
            float2 lo = *(float2*)&acc[j][0];
            float2 hi = *(float2*)&acc[j][1];
            *(float4*)&g_z[gn * NC + lane * 4] = make_float4(lo.x, lo.y, hi.x, hi.y);
        }
    }
}

// ---------------- aggregation + epilogue -------------------------------------
// One warp per node; lane owns 4 channels as two packed f32x2 accumulator
// pairs (4 independent dep chains). exp(z_s*z_d) via exp2 with log2e folded
// into the node-resident operand. No max-shift needed (|e|<~35, fp32-safe);
// identical real-arithmetic result to the reference's shifted softmax.
__device__ __forceinline__ float elu1(float v) {
    return v > 0.f ? v : expm1f(v);
}

__global__ void __launch_bounds__(256) gat_agg(const float* __restrict__ hin,
                                               const float* __restrict__ snorm,
                                               float* __restrict__ out) {
    const int gw   = (blockIdx.x * blockDim.x + threadIdx.x) >> 5;
    const int lane = threadIdx.x & 31;
    if (gw >= NV) return;
    const int node = gw;

    const ulonglong2 zd = *(const ulonglong2*)&g_z[node * NC + lane * 4];
    const u64 l2  = vsplat(1.4426950408889634f);
    const u64 qa  = vmul2(zd.x, l2);     // chans lane*4+0,1, pre-scaled
    const u64 qb  = vmul2(zd.y, l2);     // chans lane*4+2,3, pre-scaled

    u64 da = 0ull, db = 0ull, na = 0ull, nb = 0ull;

    const int p0 = g_off[node];
    const int p1 = g_off[node + 1];

    int p = p0;
    for (; p + 3 < p1; p += 4) {
        int s0 = __ldg(&g_adj[p]);
        int s1 = __ldg(&g_adj[p + 1]);
        int s2 = __ldg(&g_adj[p + 2]);
        int s3 = __ldg(&g_adj[p + 3]);
        ulonglong2 z0 = *(const ulonglong2*)&g_z[s0 * NC + lane * 4];
        ulonglong2 z1 = *(const ulonglong2*)&g_z[s1 * NC + lane * 4];
        ulonglong2 z2 = *(const ulonglong2*)&g_z[s2 * NC + lane * 4];
        ulonglong2 z3 = *(const ulonglong2*)&g_z[s3 * NC + lane * 4];
#pragma unroll
        for (int u = 0; u < 4; ++u) {
            ulonglong2 zz = (u == 0) ? z0 : (u == 1) ? z1 : (u == 2) ? z2 : z3;
            u64 ea = vmul2(zz.x, qa);
            u64 eb = vmul2(zz.y, qb);
            float a0, a1, b0, b1;
            vunpack(ea, a0, a1);
            vunpack(eb, b0, b1);
            a0 = exp2f(a0); a1 = exp2f(a1);
            b0 = exp2f(b0); b1 = exp2f(b1);
            u64 xa = vpack(a0, a1);
            u64 xb = vpack(b0, b1);
            da = vadd2(da, xa);
            db = vadd2(db, xb);
            na = vfma2(xa, zz.x, na);
            nb = vfma2(xb, zz.y, nb);
        }
    }
    for (; p < p1; ++p) {
        int s0 = __ldg(&g_adj[p]);
        ulonglong2 zz = *(const ulonglong2*)&g_z[s0 * NC + lane * 4];
        u64 ea = vmul2(zz.x, qa);
        u64 eb = vmul2(zz.y, qb);
        float a0, a1, b0, b1;
        vunpack(ea, a0, a1);
        vunpack(eb, b0, b1);
        a0 = exp2f(a0); a1 = exp2f(a1);
        b0 = exp2f(b0); b1 = exp2f(b1);
        u64 xa = vpack(a0, a1);
        u64 xb = vpack(b0, b1);
        da = vadd2(da, xa);
        db = vadd2(db, xb);
        na = vfma2(xa, zz.x, na);
        nb = vfma2(xb, zz.y, nb);
    }

    const float sn = __ldg(&snorm[node]);
    const float4 hv = *(const float4*)&hin[node * NC + lane * 4];

    float dx, dy, dz, dw, ax, ay, az, aw;
    vunpack(da, dx, dy);
    vunpack(db, dz, dw);
    vunpack(na, ax, ay);
    vunpack(nb, az, aw);

    float rx = (dx > 0.f) ? __fdividef(1.f, dx) : 0.f;
    float ry = (dy > 0.f) ? __fdividef(1.f, dy) : 0.f;
    float rz = (dz > 0.f) ? __fdividef(1.f, dz) : 0.f;
    float rw = (dw > 0.f) ? __fdividef(1.f, dw) : 0.f;

    float4 o;
    o.x = hv.x + elu1(ax * rx * sn);
    o.y = hv.y + elu1(ay * ry * sn);
    o.z = hv.z + elu1(az * rz * sn);
    o.w = hv.w + elu1(aw * rw * sn);

    *(float4*)&out[node * NC + lane * 4] = o;
}

// ---------------- launch ----------------------------------------------------
// Capture-safe fork/join: s2 chain = gemm -> evJoin -> (wait evScat) ->
// reset -> evTail; stream 0 waits evJoin before agg, evTail after agg.
extern "C" void kernel_launch(void* const* d_in, const int* in_sizes, int n_in,
                              void* d_out, int out_size) {
    const float* hin   = (const float*)d_in[0];   // [N,128]
    const float* snorm = (const float*)d_in[1];   // [N,1]
    const float* Wfc   = (const float*)d_in[2];   // [8,128,16]
    const int*   src   = (const int*)d_in[3];     // [E]
    const int*   dst   = (const int*)d_in[4];     // [E]
    float* out = (float*)d_out;                   // [N,128]

    const int gemm_smem = (NK * NC + TM * NK) * sizeof(float);   // 96 KB

    static int init_done = 0;
    static cudaStream_t s2 = 0;
    static cudaEvent_t evFork = 0, evJoin = 0, evScat = 0, evTail = 0;
    if (!init_done) {
        cudaFuncSetAttribute(gat_gemm, cudaFuncAttributeMaxDynamicSharedMemorySize,
                             gemm_smem);
        if (cudaStreamCreateWithFlags(&s2, cudaStreamNonBlocking) != cudaSuccess)
            s2 = 0;
        if (s2) {
            if (cudaEventCreateWithFlags(&evFork, cudaEventDisableTiming) != cudaSuccess ||
                cudaEventCreateWithFlags(&evJoin, cudaEventDisableTiming) != cudaSuccess ||
                cudaEventCreateWithFlags(&evScat, cudaEventDisableTiming) != cudaSuccess ||
                cudaEventCreateWithFlags(&evTail, cudaEventDisableTiming) != cudaSuccess) {
                s2 = 0;   // deterministic serial fallback
            }
        }
        init_done = 1;
    }

    if (s2) {
        cudaEventRecord(evFork, 0);
        cudaStreamWaitEvent(s2, evFork, 0);
        gat_gemm<<<(NV + TM - 1) / TM, 256, gemm_smem, s2>>>(hin, Wfc);
        cudaEventRecord(evJoin, s2);
    }

    gat_hist<<<(NE / 4 + 255) / 256, 256>>>((const int4*)dst);
    gat_scan_local<<<NSB, SCB>>>();
    gat_scan_apply<<<NSB, SCB>>>();
    gat_scatter<<<(NE + 255) / 256, 256>>>(src, dst);

    if (s2) {
        cudaEventRecord(evScat, 0);
        cudaStreamWaitEvent(s2, evScat, 0);
        gat_reset<<<(NV + 255) / 256, 256, 0, s2>>>();
        cudaEventRecord(evTail, s2);
        cudaStreamWaitEvent(0, evJoin, 0);
        gat_agg<<<(NV * 32 + 255) / 256, 256>>>(hin, snorm, out);
        cudaStreamWaitEvent(0, evTail, 0);
    } else {
        gat_gemm<<<(NV + TM - 1) / TM, 256, gemm_smem>>>(hin, Wfc);
        gat_agg<<<(NV * 32 + 255) / 256, 256>>>(hin, snorm, out);
        gat_reset<<<(NV + 255) / 256, 256>>>();
    }
}

// round 16
// speedup vs baseline: 1.0508x; 1.0302x over previous
#include <cuda_runtime.h>
#include <cuda_bf16.h>
#include <cstdint>

// GAT layer, fixed shapes: N=50000, E=800000, C=H*D=128, K=128.
#define NV 50000
#define NE 800000
#define NC 128
#define NK 128

typedef unsigned long long u64;

// ---------------- device scratch (zero-initialized at module load) ----------
__device__ float g_z[NV * NC];           // projected features [N,128]
__device__ int   g_cnt[NV];              // degree histogram (tail-zeroed)
__device__ int   g_off[NV + 1];          // CSR row offsets by dst
__device__ int   g_adj[NE];              // src ids grouped by dst
__device__ int   g_rank[NE];             // per-edge rank within its dst bucket

#define SCB  512
#define NSB  ((NV + SCB - 1) / SCB)      // 98
__device__ int g_btot[NSB];

// ---------------- f32x2 helpers (GEMM only) ----------------------------------
__device__ __forceinline__ u64 vfma2(u64 a, u64 b, u64 c) {
    u64 r;
    asm("fma.rn.f32x2 %0, %1, %2, %3;" : "=l"(r) : "l"(a), "l"(b), "l"(c));
    return r;
}
__device__ __forceinline__ u64 vsplat(float x) {
    u64 r;
    asm("mov.b64 %0, {%1, %1};" : "=l"(r) : "f"(x));
    return r;
}

// ---------------- CSR construction ------------------------------------------
// Hist also RECORDS each edge's arrival rank — the scatter pass then needs no
// atomics at all (pos = off[dst] + rank). g_cnt must be zero on entry.
__global__ void gat_hist(const int4* __restrict__ dst4, int4* __restrict__ rank4) {
    int t = blockIdx.x * blockDim.x + threadIdx.x;
    if (t < NE / 4) {
        int4 d = __ldg(&dst4[t]);
        int4 r;
        r.x = atomicAdd(&g_cnt[d.x], 1);
        r.y = atomicAdd(&g_cnt[d.y], 1);
        r.z = atomicAdd(&g_cnt[d.z], 1);
        r.w = atomicAdd(&g_cnt[d.w], 1);
        rank4[t] = r;
    }
}

__global__ void __launch_bounds__(SCB) gat_scan_local() {
    __shared__ int s[SCB];
    const int b = blockIdx.x, t = threadIdx.x, i = b * SCB + t;
    int v = (i < NV) ? g_cnt[i] : 0;
    s[t] = v;
    __syncthreads();
    for (int o = 1; o < SCB; o <<= 1) {
        int x = (t >= o) ? s[t - o] : 0;
        __syncthreads();
        s[t] += x;
        __syncthreads();
    }
    if (i < NV) g_off[i] = s[t] - v;
    if (t == SCB - 1) g_btot[b] = s[t];
}

// Each block redundantly scans all 98 block totals (no inter-block spin).
__global__ void __launch_bounds__(SCB) gat_scan_apply() {
    __shared__ int sb[128];
    const int b = blockIdx.x, t = threadIdx.x, i = b * SCB + t;

    if (t < 128) sb[t] = (t < NSB) ? g_btot[t] : 0;
    __syncthreads();
    for (int o = 1; o < 128; o <<= 1) {
        int x = (t < 128 && t >= o) ? sb[t - o] : 0;
        __syncthreads();
        if (t < 128) sb[t] += x;
        __syncthreads();
    }
    const int boff = (b > 0) ? sb[b - 1] : 0;

    if (i < NV) g_off[i] = g_off[i] + boff;
    if (b == NSB - 1 && t == 0) g_off[NV] = NE;
}

// Atomic-free scatter: pos = off[dst] + rank. off table (200KB) caches in L1.
__global__ void gat_scatter(const int4* __restrict__ src4,
                            const int4* __restrict__ dst4,
                            const int4* __restrict__ rank4) {
    int t = blockIdx.x * blockDim.x + threadIdx.x;
    if (t < NE / 4) {
        int4 d = __ldg(&dst4[t]);
        int4 s = __ldg(&src4[t]);
        int4 r = __ldg(&rank4[t]);
        g_adj[__ldg(&g_off[d.x]) + r.x] = s.x;
        g_adj[__ldg(&g_off[d.y]) + r.y] = s.y;
        g_adj[__ldg(&g_off[d.z]) + r.z] = s.z;
        g_adj[__ldg(&g_off[d.w]) + r.w] = s.w;
    }
}

__global__ void gat_reset() {
    int i = blockIdx.x * blockDim.x + threadIdx.x;
    if (i < NV) g_cnt[i] = 0;
}

// ---------------- GEMM via packed fma.rn.f32x2 ------------------------------
#define TM 64

__global__ void __launch_bounds__(256) gat_gemm(const float* __restrict__ hin,
                                                const float* __restrict__ Wfc) {
    extern __shared__ float smem[];
    float* sW = smem;                   // [128][128]  sW[k*128 + c]
    float* sH = smem + NK * NC;         // [64][128]   sH[row*128 + k]

    const int tid  = threadIdx.x;
    const int lane = tid & 31;
    const int warp = tid >> 5;
    const int base = blockIdx.x * TM;
    const int r0   = warp * 8;

    {
        const float4* W4 = (const float4*)Wfc;
        float4* sW4 = (float4*)sW;
        for (int g = tid; g < NK * NC / 4; g += 256) {
            int k  = g >> 5;
            int hh = (g >> 2) & 7;
            int dq = g & 3;
            sW4[g] = W4[hh * 512 + k * 4 + dq];
        }
    }
    {
        const float4* H4 = (const float4*)hin;
        float4* sH4 = (float4*)sH;
        for (int g = tid; g < TM * NK / 4; g += 256) {
            int row = g >> 5;
            int kq  = g & 31;
            int gn  = base + row;
            sH4[g] = (gn < NV) ? H4[gn * 32 + kq]
                               : make_float4(0.f, 0.f, 0.f, 0.f);
        }
    }
    __syncthreads();

    u64 acc[8][2];
#pragma unroll
    for (int j = 0; j < 8; ++j) { acc[j][0] = 0ull; acc[j][1] = 0ull; }

    for (int k = 0; k < NK; k += 4) {
        u64 w2[4][2];
#pragma unroll
        for (int kk = 0; kk < 4; ++kk) {
            ulonglong2 wv = *(const ulonglong2*)&sW[(k + kk) * NC + lane * 4];
            w2[kk][0] = wv.x;
            w2[kk][1] = wv.y;
        }
#pragma unroll
        for (int j = 0; j < 8; ++j) {
            const float4 hj = *(const float4*)&sH[(r0 + j) * NK + k];
            u64 h0 = vsplat(hj.x), h1 = vsplat(hj.y);
            u64 h2 = vsplat(hj.z), h3 = vsplat(hj.w);
            acc[j][0] = vfma2(h0, w2[0][0], acc[j][0]);
            acc[j][1] = vfma2(h0, w2[0][1], acc[j][1]);
            acc[j][0] = vfma2(h1, w2[1][0], acc[j][0]);
            acc[j][1] = vfma2(h1, w2[1][1], acc[j][1]);
            acc[j][0] = vfma2(h2, w2[2][0], acc[j][0]);
            acc[j][1] = vfma2(h2, w2[2][1], acc[j][1]);
            acc[j][0] = vfma2(h3, w2[3][0], acc[j][0]);
            acc[j][1] = vfma2(h3, w2[3][1], acc[j][1]);
        }
    }

#pragma unroll
    for (int j = 0; j < 8; ++j) {
        int gn = base + r0 + j;
        if (gn < NV) {
            float2 lo = *(float2*)&acc[j][0];
            float2 hi = *(float2*)&acc[j][1];
            *(float4*)&g_z[gn * NC + lane * 4] = make_float4(lo.x, lo.y, hi.x, hi.y);
        }
    }
}

// ---------------- aggregation + epilogue (R10 scalar form — proven best) ----
__device__ __forceinline__ float elu1(float v) {
    return v > 0.f ? v : expm1f(v);
}

__device__ __forceinline__ void edge_accum(const float4 za, const float4 zds,
                                           float& dx, float& dy, float& dz, float& dw,
                                           float& nx, float& ny, float& nz, float& nw) {
    float ex;
    ex = exp2f(za.x * zds.x); dx += ex; nx += ex * za.x;
    ex = exp2f(za.y * zds.y); dy += ex; ny += ex * za.y;
    ex = exp2f(za.z * zds.z); dz += ex; nz += ex * za.z;
    ex = exp2f(za.w * zds.w); dw += ex; nw += ex * za.w;
}

__global__ void __launch_bounds__(256) gat_agg(const float* __restrict__ hin,
                                               const float* __restrict__ snorm,
                                               float* __restrict__ out) {
    const int gw   = (blockIdx.x * blockDim.x + threadIdx.x) >> 5;
    const int lane = threadIdx.x & 31;
    if (gw >= NV) return;
    const int node = gw;

    const float LOG2E = 1.4426950408889634f;
    float4 zds = *(const float4*)&g_z[node * NC + lane * 4];
    zds.x *= LOG2E; zds.y *= LOG2E; zds.z *= LOG2E; zds.w *= LOG2E;

    float dx = 0.f, dy = 0.f, dz = 0.f, dw = 0.f;
    float nx = 0.f, ny = 0.f, nz = 0.f, nw = 0.f;

    const int p0 = g_off[node];
    const int p1 = g_off[node + 1];

    int p = p0;
    for (; p + 3 < p1; p += 4) {
        int s0 = __ldg(&g_adj[p]);
        int s1 = __ldg(&g_adj[p + 1]);
        int s2 = __ldg(&g_adj[p + 2]);
        int s3 = __ldg(&g_adj[p + 3]);
        float4 z0 = *(const float4*)&g_z[s0 * NC + lane * 4];
        float4 z1 = *(const float4*)&g_z[s1 * NC + lane * 4];
        float4 z2 = *(const float4*)&g_z[s2 * NC + lane * 4];
        float4 z3 = *(const float4*)&g_z[s3 * NC + lane * 4];
        edge_accum(z0, zds, dx, dy, dz, dw, nx, ny, nz, nw);
        edge_accum(z1, zds, dx, dy, dz, dw, nx, ny, nz, nw);
        edge_accum(z2, zds, dx, dy, dz, dw, nx, ny, nz, nw);
        edge_accum(z3, zds, dx, dy, dz, dw, nx, ny, nz, nw);
    }
    for (; p < p1; ++p) {
        int s0 = __ldg(&g_adj[p]);
        float4 z0 = *(const float4*)&g_z[s0 * NC + lane * 4];
        edge_accum(z0, zds, dx, dy, dz, dw, nx, ny, nz, nw);
    }

    const float sn = __ldg(&snorm[node]);
    float4 hv = *(const float4*)&hin[node * NC + lane * 4];

    float rx = (dx > 0.f) ? __fdividef(1.f, dx) : 0.f;
    float ry = (dy > 0.f) ? __fdividef(1.f, dy) : 0.f;
    float rz = (dz > 0.f) ? __fdividef(1.f, dz) : 0.f;
    float rw = (dw > 0.f) ? __fdividef(1.f, dw) : 0.f;

    float4 o;
    o.x = hv.x + elu1(nx * rx * sn);
    o.y = hv.y + elu1(ny * ry * sn);
    o.z = hv.z + elu1(nz * rz * sn);
    o.w = hv.w + elu1(nw * rw * sn);

    *(float4*)&out[node * NC + lane * 4] = o;
}

// ---------------- launch ----------------------------------------------------
// Capture-safe fork/join: s2 chain = gemm -> evJoin -> (wait evScat) ->
// reset -> evTail; stream 0 waits evJoin before agg, evTail after agg.
extern "C" void kernel_launch(void* const* d_in, const int* in_sizes, int n_in,
                              void* d_out, int out_size) {
    const float* hin   = (const float*)d_in[0];   // [N,128]
    const float* snorm = (const float*)d_in[1];   // [N,1]
    const float* Wfc   = (const float*)d_in[2];   // [8,128,16]
    const int*   src   = (const int*)d_in[3];     // [E]
    const int*   dst   = (const int*)d_in[4];     // [E]
    float* out = (float*)d_out;                   // [N,128]

    const int gemm_smem = (NK * NC + TM * NK) * sizeof(float);   // 96 KB

    static int init_done = 0;
    static cudaStream_t s2 = 0;
    static cudaEvent_t evFork = 0, evJoin = 0, evScat = 0, evTail = 0;
    if (!init_done) {
        cudaFuncSetAttribute(gat_gemm, cudaFuncAttributeMaxDynamicSharedMemorySize,
                             gemm_smem);
        if (cudaStreamCreateWithFlags(&s2, cudaStreamNonBlocking) != cudaSuccess)
            s2 = 0;
        if (s2) {
            if (cudaEventCreateWithFlags(&evFork, cudaEventDisableTiming) != cudaSuccess ||
                cudaEventCreateWithFlags(&evJoin, cudaEventDisableTiming) != cudaSuccess ||
                cudaEventCreateWithFlags(&evScat, cudaEventDisableTiming) != cudaSuccess ||
                cudaEventCreateWithFlags(&evTail, cudaEventDisableTiming) != cudaSuccess) {
                s2 = 0;   // deterministic serial fallback
            }
        }
        init_done = 1;
    }

    // g_rank lives in device scratch; reuse as the int4 target.
    int4* rank4 = nullptr;
    cudaGetSymbolAddress((void**)&rank4, g_rank);

    if (s2) {
        cudaEventRecord(evFork, 0);
        cudaStreamWaitEvent(s2, evFork, 0);
        gat_gemm<<<(NV + TM - 1) / TM, 256, gemm_smem, s2>>>(hin, Wfc);
        cudaEventRecord(evJoin, s2);
    }

    gat_hist<<<(NE / 4 + 255) / 256, 256>>>((const int4*)dst, rank4);
    gat_scan_local<<<NSB, SCB>>>();
    gat_scan_apply<<<NSB, SCB>>>();
    gat_scatter<<<(NE / 4 + 255) / 256, 256>>>((const int4*)src, (const int4*)dst,
                                               (const int4*)rank4);

    if (s2) {
        cudaEventRecord(evScat, 0);
        cudaStreamWaitEvent(s2, evScat, 0);
        gat_reset<<<(NV + 255) / 256, 256, 0, s2>>>();
        cudaEventRecord(evTail, s2);
        cudaStreamWaitEvent(0, evJoin, 0);
        gat_agg<<<(NV * 32 + 255) / 256, 256>>>(hin, snorm, out);
        cudaStreamWaitEvent(0, evTail, 0);
    } else {
        gat_gemm<<<(NV + TM - 1) / TM, 256, gemm_smem>>>(hin, Wfc);
        gat_agg<<<(NV * 32 + 255) / 256, 256>>>(hin, snorm, out);
        gat_reset<<<(NV + 255) / 256, 256>>>();
    }
}